// round 16
// baseline (speedup 1.0000x reference)
#include <cuda_runtime.h>
#include <cuda_bf16.h>
#include <cstdint>

#define V_  50257
#define H_  768
#define B_  16
#define T_  128
#define G_  3072          // 4*H
#define KX  1536          // 2*H
#define MROWS 2048        // B*T
#define NT_  393          // logits n-tiles = ceil(V/128)

#define LSTM_BLOCKS 128
#define LSTM_WARPS  6     // units per block; 128*6 = 768 = H_

// ================= scratch (no cudaMalloc allowed) =================
__device__ float g_xg[(long)MROWS * G_];                 // input-side gate projections
__device__ float g_lse[MROWS];                           // per-row log-sum-exp
__device__ float g_part[(long)MROWS * NT_];              // per (row, n-tile) exp-sum partials
__device__ int   g_last[B_];
__device__ unsigned g_bar;                               // grid barrier counter
__device__ __nv_bfloat16 g_whi[(long)V_ * H_];           // lm_w hi (bf16)
__device__ __nv_bfloat16 g_ahi[(long)MROWS * H_];        // hiddens hi (bf16)
__device__ __nv_bfloat16 g_xah[(long)MROWS * KX];        // [emb||app] hi
__device__ __nv_bfloat16 g_xal[(long)MROWS * KX];        // [emb||app] lo
__device__ __nv_bfloat16 g_wihh[(long)G_ * KX];          // W_ih hi
__device__ __nv_bfloat16 g_wihl[(long)G_ * KX];          // W_ih lo

// ================= small ptx helpers (baseline PTX only) =================
__device__ __forceinline__ uint32_t smem_to_u32(const void* p) {
    uint32_t a;
    asm("{ .reg .u64 t; cvta.to.shared.u64 t, %1; cvt.u32.u64 %0, t; }" : "=r"(a) : "l"(p));
    return a;
}
__device__ __forceinline__ void cpasync16(uint32_t dst, const void* src, uint32_t sz) {
    asm volatile("cp.async.cg.shared.global [%0], [%1], 16, %2;\n"
        :: "r"(dst), "l"(src), "r"(sz) : "memory");
}
__device__ __forceinline__ void ldm_x4(uint32_t addr, uint32_t* r) {
    asm volatile("ldmatrix.sync.aligned.m8n8.x4.shared.b16 {%0,%1,%2,%3}, [%4];"
        : "=r"(r[0]), "=r"(r[1]), "=r"(r[2]), "=r"(r[3]) : "r"(addr));
}
__device__ __forceinline__ void mma16816(float* d, const uint32_t* a, const uint32_t* b) {
    asm volatile("mma.sync.aligned.m16n8k16.row.col.f32.bf16.bf16.f32 "
        "{%0,%1,%2,%3}, {%4,%5,%6,%7}, {%8,%9}, {%0,%1,%2,%3};"
        : "+f"(d[0]), "+f"(d[1]), "+f"(d[2]), "+f"(d[3])
        : "r"(a[0]), "r"(a[1]), "r"(a[2]), "r"(a[3]), "r"(b[0]), "r"(b[1]));
}
__device__ __forceinline__ unsigned ld_acq(const unsigned* p) {
    unsigned v;
    asm volatile("ld.acquire.gpu.global.u32 %0, [%1];" : "=r"(v) : "l"(p) : "memory");
    return v;
}
__device__ __forceinline__ void red_release_add(unsigned* p, unsigned v) {
    asm volatile("red.release.gpu.global.add.u32 [%0], %1;" :: "l"(p), "r"(v) : "memory");
}
// packed f32x2 FMA (sm_100-family): d = a*b + d on two lanes at once
__device__ __forceinline__ void ffma2(uint64_t& d, uint64_t a, uint64_t b) {
    asm("fma.rn.f32x2 %0, %1, %2, %0;" : "+l"(d) : "l"(a), "l"(b));
}
__device__ __forceinline__ uint64_t pk(float lo, float hi) {
    uint64_t r;
    asm("mov.b64 %0, {%1, %2};" : "=l"(r) : "f"(lo), "f"(hi));
    return r;
}
__device__ __forceinline__ uint64_t pk2(float v) { return pk(v, v); }
__device__ __forceinline__ void unpk(uint64_t p, float& lo, float& hi) {
    asm("mov.b64 {%0, %1}, %2;" : "=f"(lo), "=f"(hi) : "l"(p));
}

// ================= fast exp (FMA-only; valid for x in [-20, ~80]) =================
__device__ __forceinline__ float fexp(float x) {
    x = fmaxf(x, -20.0f);
    float t  = x * 1.4426950408889634f;
    float z  = t + 12582912.0f;
    float nf = z - 12582912.0f;
    float f  = t - nf;
    int   n  = (int)nf;
    float p = fmaf(0.00133335581f, f, 0.00961812911f);
    p = fmaf(p, f, 0.0555041087f);
    p = fmaf(p, f, 0.240226507f);
    p = fmaf(p, f, 0.69314718056f);
    p = fmaf(p, f, 1.0f);
    return p * __int_as_float((n + 127) << 23);
}

// ================= setup =================
__global__ void setup_k(const int* __restrict__ mask) {
    int idx = threadIdx.x;
    if (idx < B_) {
        int s = 0;
        for (int t = 0; t < T_; t++) s += mask[idx * T_ + t];
        g_last[idx] = s - 1;
    }
    if (idx == B_) g_bar = 0u;
}

// ================= hi/lo bf16 conversions =================
__global__ void conv_k(const float* __restrict__ src, __nv_bfloat16* __restrict__ hi,
                       __nv_bfloat16* __restrict__ lo, long n4) {
    long i = (long)blockIdx.x * 256 + threadIdx.x;
    long stride = (long)gridDim.x * 256;
    for (; i < n4; i += stride) {
        float4 v = ((const float4*)src)[i];
        __nv_bfloat16 h0 = __float2bfloat16(v.x), h1 = __float2bfloat16(v.y);
        __nv_bfloat16 h2 = __float2bfloat16(v.z), h3 = __float2bfloat16(v.w);
        __nv_bfloat16 l0 = __float2bfloat16(v.x - __bfloat162float(h0));
        __nv_bfloat16 l1 = __float2bfloat16(v.y - __bfloat162float(h1));
        __nv_bfloat16 l2 = __float2bfloat16(v.z - __bfloat162float(h2));
        __nv_bfloat16 l3 = __float2bfloat16(v.w - __bfloat162float(h3));
        ((__nv_bfloat162*)hi)[i * 2 + 0] = __nv_bfloat162(h0, h1);
        ((__nv_bfloat162*)hi)[i * 2 + 1] = __nv_bfloat162(h2, h3);
        ((__nv_bfloat162*)lo)[i * 2 + 0] = __nv_bfloat162(l0, l1);
        ((__nv_bfloat162*)lo)[i * 2 + 1] = __nv_bfloat162(l2, l3);
    }
}

// hi-only conversion (for lm_w: 1-term logits GEMM needs no residual)
__global__ void conv_hi(const float* __restrict__ src, __nv_bfloat16* __restrict__ hi, long n4) {
    long i = (long)blockIdx.x * 256 + threadIdx.x;
    long stride = (long)gridDim.x * 256;
    for (; i < n4; i += stride) {
        float4 v = ((const float4*)src)[i];
        ((__nv_bfloat162*)hi)[i * 2 + 0] =
            __nv_bfloat162(__float2bfloat16(v.x), __float2bfloat16(v.y));
        ((__nv_bfloat162*)hi)[i * 2 + 1] =
            __nv_bfloat162(__float2bfloat16(v.z), __float2bfloat16(v.w));
    }
}

// build [emb(ids) || append] as hi/lo bf16, rows = MROWS, K = KX
__global__ void conv_gather(const int* __restrict__ ids, const float* __restrict__ emb,
                            const float* __restrict__ app,
                            __nv_bfloat16* __restrict__ hi, __nv_bfloat16* __restrict__ lo) {
    long total = (long)MROWS * (KX / 4);
    long i = (long)blockIdx.x * 256 + threadIdx.x;
    long stride = (long)gridDim.x * 256;
    for (; i < total; i += stride) {
        int m = (int)(i / (KX / 4));
        int q = (int)(i - (long)m * (KX / 4));
        int k = q * 4;
        const float* p;
        if (k < H_) p = emb + (long)ids[m] * H_ + k;
        else        p = app + (long)(m >> 7) * H_ + (k - H_);
        float4 v = *(const float4*)p;
        __nv_bfloat16 h0 = __float2bfloat16(v.x), h1 = __float2bfloat16(v.y);
        __nv_bfloat16 h2 = __float2bfloat16(v.z), h3 = __float2bfloat16(v.w);
        __nv_bfloat16 l0 = __float2bfloat16(v.x - __bfloat162float(h0));
        __nv_bfloat16 l1 = __float2bfloat16(v.y - __bfloat162float(h1));
        __nv_bfloat16 l2 = __float2bfloat16(v.z - __bfloat162float(h2));
        __nv_bfloat16 l3 = __float2bfloat16(v.w - __bfloat162float(h3));
        long o = (long)m * (KX / 2) + q * 2;
        ((__nv_bfloat162*)hi)[o + 0] = __nv_bfloat162(h0, h1);
        ((__nv_bfloat162*)hi)[o + 1] = __nv_bfloat162(h2, h3);
        ((__nv_bfloat162*)lo)[o + 0] = __nv_bfloat162(l0, l1);
        ((__nv_bfloat162*)lo)[o + 1] = __nv_bfloat162(l2, l3);
    }
}

// ================= HMMA GEMM (templated terms/stages/fused-sum): C = A @ B^T + bias ====
// Block 128x128, warp tile 64x32 (8 warps 2m x 4n), BK=32, NST-stage cp.async pipeline,
// ONE __syncthreads per K-chunk.
// NTERMS=3: AhBh+AhBl+AlBh (1 CTA/SM). NTERMS=1: AhBh only (2 CTAs/SM).
// FUSE: additionally emits deterministic per-(row, n-tile) sum-of-exp partials to part[].
#define LDSW  80                     // padded row stride bytes (64B data + 16B pad)
#define TILEB (128 * LDSW)           // 10240 B per 128-row tile

template<int NTERMS, int NST, bool FUSE>
__global__ __launch_bounds__(256, (NTERMS == 1 ? 2 : 1)) void hmma_gemm(
    const __nv_bfloat16* __restrict__ Ah, const __nv_bfloat16* __restrict__ Al,
    const __nv_bfloat16* __restrict__ Bh, const __nv_bfloat16* __restrict__ Bl,
    const float* __restrict__ bias, float* __restrict__ C,
    int K, int Nvalid, float* __restrict__ part)
{
    constexpr int NMAT  = (NTERMS == 3) ? 4 : (NTERMS == 2 ? 3 : 2);
    constexpr int STAGE = NMAT * TILEB;
    // stage layout: Ah @0, Bh @TILEB, [Bl @2*TILEB], [Al @3*TILEB]

    extern __shared__ __align__(128) char smem[];
    uint32_t sb = smem_to_u32(smem);
    int tid = threadIdx.x;
    int lane = tid & 31, wid = tid >> 5;
    int wm = wid & 1, wn = wid >> 1;
    int m0 = blockIdx.x * 128;          // m-fast for B-tile L2 reuse
    int n0 = blockIdx.y * 128;
    int NK = K >> 5;

    float acc[4][4][4];
#pragma unroll
    for (int a = 0; a < 4; a++)
#pragma unroll
        for (int b = 0; b < 4; b++)
#pragma unroll
            for (int c = 0; c < 4; c++) acc[a][b][c] = 0.0f;

    int lrow = tid >> 2;     // 0..63
    int lq   = tid & 3;

    auto load_stage = [&](int stg) {
        int k0 = stg << 5;
        uint32_t db = sb + (stg % NST) * STAGE;
#pragma unroll
        for (int half = 0; half < 2; half++) {
            int r = half * 64 + lrow;
            uint32_t dof = (uint32_t)(r * LDSW + lq * 16);
            long asrc = (long)(m0 + r) * K + k0 + lq * 8;
            cpasync16(db + dof, Ah + asrc, 16);
            if (NTERMS == 3) cpasync16(db + 3 * TILEB + dof, Al + asrc, 16);
            int n = n0 + r;
            uint32_t sz = 16;
            if (n >= Nvalid) { n = 0; sz = 0; }
            long bsrc = (long)n * K + k0 + lq * 8;
            cpasync16(db + TILEB + dof, Bh + bsrc, sz);
            if (NTERMS >= 2) cpasync16(db + 2 * TILEB + dof, Bl + bsrc, sz);
        }
    };

    // prologue: fill NST-1 stages
#pragma unroll
    for (int s = 0; s < NST - 1; s++) {
        if (s < NK) load_stage(s);
        asm volatile("cp.async.commit_group;" ::: "memory");
    }

    int a_row = lane & 15;
    int a_kh  = (lane >> 4) << 3;
    int b_g   = lane >> 3;
    int b_nr  = ((b_g >> 1) << 3) + (lane & 7);
    int b_kh  = (b_g & 1) << 3;

    for (int c = 0; c < NK; c++) {
        asm volatile("cp.async.wait_group %0;" :: "n"(NST - 2) : "memory");
        __syncthreads();

        // refill stage c+NST-1 (that buffer was last read in chunk c-1; safe after sync)
        if (c + NST - 1 < NK) load_stage(c + NST - 1);
        asm volatile("cp.async.commit_group;" ::: "memory");

        uint32_t aB = sb + (c % NST) * STAGE;
#pragma unroll
        for (int kk = 0; kk < 32; kk += 16) {
            uint32_t bh[8], bl[8], ah[16], al[16];
#pragma unroll
            for (int f2 = 0; f2 < 2; f2++) {
                uint32_t off = (uint32_t)((wn * 32 + f2 * 16 + b_nr) * LDSW + (kk + b_kh) * 2);
                ldm_x4(aB + TILEB + off, &bh[f2 * 4]);
                if (NTERMS >= 2) ldm_x4(aB + 2 * TILEB + off, &bl[f2 * 4]);
            }
#pragma unroll
            for (int fm = 0; fm < 4; fm++) {
                uint32_t off = (uint32_t)((wm * 64 + fm * 16 + a_row) * LDSW + (kk + a_kh) * 2);
                ldm_x4(aB + off, &ah[fm * 4]);
                if (NTERMS == 3) ldm_x4(aB + 3 * TILEB + off, &al[fm * 4]);
            }
#pragma unroll
            for (int fm = 0; fm < 4; fm++)
#pragma unroll
                for (int fn = 0; fn < 4; fn++) {
                    mma16816(acc[fm][fn], &ah[fm * 4], &bh[fn * 2]);
                    if (NTERMS >= 2) mma16816(acc[fm][fn], &ah[fm * 4], &bl[fn * 2]);
                    if (NTERMS == 3) mma16816(acc[fm][fn], &al[fm * 4], &bh[fn * 2]);
                }
        }
    }

    // epilogue: direct stores + bias; FUSE also accumulates sum-of-exp per row
    int mbase = m0 + wm * 64 + (lane >> 2);
    int nbase = n0 + wn * 32 + ((lane & 3) << 1);
    float es_lo[4], es_hi[4];
    if (FUSE) {
#pragma unroll
        for (int i = 0; i < 4; i++) { es_lo[i] = 0.0f; es_hi[i] = 0.0f; }
    }
#pragma unroll
    for (int fm = 0; fm < 4; fm++) {
#pragma unroll
        for (int fn = 0; fn < 4; fn++) {
            int m = mbase + fm * 16;
            int n = nbase + fn * 8;
            float* d = acc[fm][fn];
            if (n < Nvalid) {
                float bv = bias[n];
                float v0 = d[0] + bv, v2 = d[2] + bv;
                C[(long)m * Nvalid + n]       = v0;
                C[(long)(m + 8) * Nvalid + n] = v2;
                if (FUSE) { es_lo[fm] += fexp(v0); es_hi[fm] += fexp(v2); }
            }
            if (n + 1 < Nvalid) {
                float bv = bias[n + 1];
                float v1 = d[1] + bv, v3 = d[3] + bv;
                C[(long)m * Nvalid + n + 1]       = v1;
                C[(long)(m + 8) * Nvalid + n + 1] = v3;
                if (FUSE) { es_lo[fm] += fexp(v1); es_hi[fm] += fexp(v3); }
            }
        }
    }
    if (FUSE) {
        // deterministic: quad-shfl -> one writer per (row, wn) -> fixed-order sum
        __syncthreads();                 // smem stages no longer needed
        float* rsum = (float*)smem;      // [128][4]
#pragma unroll
        for (int fm = 0; fm < 4; fm++) {
            float el = es_lo[fm], eh = es_hi[fm];
            el += __shfl_xor_sync(0xffffffffu, el, 1);
            el += __shfl_xor_sync(0xffffffffu, el, 2);
            eh += __shfl_xor_sync(0xffffffffu, eh, 1);
            eh += __shfl_xor_sync(0xffffffffu, eh, 2);
            if ((lane & 3) == 0) {
                int rl = wm * 64 + fm * 16 + (lane >> 2);
                rsum[rl * 4 + wn] = el;
                rsum[(rl + 8) * 4 + wn] = eh;
            }
        }
        __syncthreads();
        if (tid < 128) {
            float s = rsum[tid * 4 + 0] + rsum[tid * 4 + 1]
                    + rsum[tid * 4 + 2] + rsum[tid * 4 + 3];
            part[(long)(m0 + tid) * NT_ + blockIdx.y] = s;
        }
    }
}

// ================= lse reduce: fixed-order sum of partials, then log =================
__global__ void lse_red() {
    int m = blockIdx.x * 256 + threadIdx.x;
    if (m < MROWS) {
        const float* p = g_part + (long)m * NT_;
        float s = 0.0f;
        for (int i = 0; i < NT_; i++) s += p[i];
        g_lse[m] = logf(s);
    }
}

// ================= final subtract =================
__global__ void sub_k(float* __restrict__ lp) {
    int m = blockIdx.x;
    float l = g_lse[m];
    float* row = lp + (long)m * V_;
    for (int j = threadIdx.x; j < V_; j += 256) row[j] -= l;
}

// ================= persistent LSTM recurrence (f32x2-packed gates GEMM) ==============
__global__ __launch_bounds__(192) void lstm_persist(
    const float* __restrict__ dh, const float* __restrict__ dctx,
    const float* __restrict__ Whh, const float* __restrict__ bhh,
    float* __restrict__ allh, float* __restrict__ selctx,
    __nv_bfloat16* __restrict__ ahi)
{
    __shared__ __align__(16) float hs[B_ * H_];
    int tid = threadIdx.x, wid = tid >> 5, lane = tid & 31;
    int u = blockIdx.x * LSTM_WARPS + wid;

    const float4* wp0 = (const float4*)(Whh + (long)(0 * H_ + u) * H_);
    const float4* wp1 = (const float4*)(Whh + (long)(1 * H_ + u) * H_);
    const float4* wp2 = (const float4*)(Whh + (long)(2 * H_ + u) * H_);
    const float4* wp3 = (const float4*)(Whh + (long)(3 * H_ + u) * H_);
    const float4* h4 = (const float4*)hs;

    float creg = 0.0f, b0r = 0.0f, b1r = 0.0f, b2r = 0.0f, b3r = 0.0f;
    float x0 = 0.f, x1 = 0.f, x2 = 0.f, x3 = 0.f;
    int lastb = 0;
    if (lane < 16) {
        creg = dctx[lane * H_ + u];
        lastb = g_last[lane];
        b0r = bhh[0 * H_ + u]; b1r = bhh[1 * H_ + u];
        b2r = bhh[2 * H_ + u]; b3r = bhh[3 * H_ + u];
        const float* xr = g_xg + ((long)lane * T_ + 0) * G_;
        x0 = xr[0 * H_ + u]; x1 = xr[1 * H_ + u];
        x2 = xr[2 * H_ + u]; x3 = xr[3 * H_ + u];
    }

    for (int t = 0; t < T_; t++) {
        float nx0 = 0.f, nx1 = 0.f, nx2 = 0.f, nx3 = 0.f;
        if (lane < 16 && t + 1 < T_) {
            const float* xr = g_xg + ((long)lane * T_ + t + 1) * G_;
            nx0 = __ldcg(xr + 0 * H_ + u); nx1 = __ldcg(xr + 1 * H_ + u);
            nx2 = __ldcg(xr + 2 * H_ + u); nx3 = __ldcg(xr + 3 * H_ + u);
        }

        if (t == 0) {
            for (int i4 = tid; i4 < B_ * H_ / 4; i4 += 192)
                ((float4*)hs)[i4] = __ldcg((const float4*)dh + i4);
        } else {
            for (int i4 = tid; i4 < B_ * H_ / 4; i4 += 192) {
                int b = i4 / (H_ / 4), q = i4 - b * (H_ / 4);
                ((float4*)hs)[i4] = __ldcg((const float4*)(allh + ((long)b * T_ + t - 1) * H_) + q);
            }
        }
        __syncthreads();

        // gates GEMM: pack batch pairs into f32x2 -> half the fma-pipe cycles
        uint64_t acc2[4][8];
#pragma unroll
        for (int g = 0; g < 4; g++)
#pragma unroll
            for (int bp = 0; bp < 8; bp++) acc2[g][bp] = 0ull;

#pragma unroll
        for (int ch = 0; ch < 6; ch++) {
            int k4 = ch * 32 + lane;
            float4 w0 = wp0[k4], w1 = wp1[k4], w2 = wp2[k4], w3 = wp3[k4];
            uint64_t w0x = pk2(w0.x), w0y = pk2(w0.y), w0z = pk2(w0.z), w0w = pk2(w0.w);
            uint64_t w1x = pk2(w1.x), w1y = pk2(w1.y), w1z = pk2(w1.z), w1w = pk2(w1.w);
            uint64_t w2x = pk2(w2.x), w2y = pk2(w2.y), w2z = pk2(w2.z), w2w = pk2(w2.w);
            uint64_t w3x = pk2(w3.x), w3y = pk2(w3.y), w3z = pk2(w3.z), w3w = pk2(w3.w);
#pragma unroll
            for (int bp = 0; bp < 8; bp++) {
                float4 hA = h4[(2 * bp) * 192 + k4];
                float4 hB = h4[(2 * bp + 1) * 192 + k4];
                uint64_t hx = pk(hA.x, hB.x), hy = pk(hA.y, hB.y);
                uint64_t hz = pk(hA.z, hB.z), hw = pk(hA.w, hB.w);
                ffma2(acc2[0][bp], w0x, hx); ffma2(acc2[0][bp], w0y, hy);
                ffma2(acc2[0][bp], w0z, hz); ffma2(acc2[0][bp], w0w, hw);
                ffma2(acc2[1][bp], w1x, hx); ffma2(acc2[1][bp], w1y, hy);
                ffma2(acc2[1][bp], w1z, hz); ffma2(acc2[1][bp], w1w, hw);
                ffma2(acc2[2][bp], w2x, hx); ffma2(acc2[2][bp], w2y, hy);
                ffma2(acc2[2][bp], w2z, hz); ffma2(acc2[2][bp], w2w, hw);
                ffma2(acc2[3][bp], w3x, hx); ffma2(acc2[3][bp], w3y, hy);
                ffma2(acc2[3][bp], w3z, hz); ffma2(acc2[3][bp], w3w, hw);
            }
        }

        float acc[4][16];
#pragma unroll
        for (int g = 0; g < 4; g++)
#pragma unroll
            for (int bp = 0; bp < 8; bp++)
                unpk(acc2[g][bp], acc[g][2 * bp], acc[g][2 * bp + 1]);

#pragma unroll
        for (int g = 0; g < 4; g++)
#pragma unroll
            for (int b = 0; b < 16; b++) {
                float v = acc[g][b];
#pragma unroll
                for (int off = 16; off; off >>= 1) v += __shfl_xor_sync(0xffffffffu, v, off);
                acc[g][b] = v;
            }

        if (lane < 16) {
            int b = lane;
            long m = (long)b * T_ + t;
            float xi = acc[0][b] + x0 + b0r;
            float xf = acc[1][b] + x1 + b1r;
            float xg = acc[2][b] + x2 + b2r;
            float xo = acc[3][b] + x3 + b3r;
            float si = 1.0f / (1.0f + expf(-xi));
            float sf = 1.0f / (1.0f + expf(-xf));
            float so = 1.0f / (1.0f + expf(-xo));
            float tg = tanhf(xg);
            creg = sf * creg + si * tg;
            float h = so * tanhf(creg);
            allh[m * H_ + u] = h;
            ahi[m * H_ + u] = __float2bfloat16(h);
            if (t == lastb) selctx[b * H_ + u] = creg;
        }
        x0 = nx0; x1 = nx1; x2 = nx2; x3 = nx3;

        if (t + 1 < T_) {
            __syncthreads();              // orders all threads' h-stores before tid0's release
            if (tid == 0) {
                red_release_add(&g_bar, 1u);   // cumulative release publishes block's writes
                unsigned tgt = (unsigned)(LSTM_BLOCKS * (t + 1));
                while (ld_acq(&g_bar) < tgt) { }
            }
            __syncthreads();
        }
    }
}

// ================= launch =================
extern "C" void kernel_launch(void* const* d_in, const int* in_sizes, int n_in,
                              void* d_out, int out_size)
{
    const int*   ids  = (const int*)d_in[0];
    const int*   mask = (const int*)d_in[1];
    const float* dh   = (const float*)d_in[2];
    const float* dc   = (const float*)d_in[3];
    const float* dapp = (const float*)d_in[4];
    const float* emb  = (const float*)d_in[5];
    const float* Wih  = (const float*)d_in[6];
    const float* Whh  = (const float*)d_in[7];
    const float* bih  = (const float*)d_in[8];
    const float* bhh  = (const float*)d_in[9];
    const float* lmw  = (const float*)d_in[10];
    const float* lmb  = (const float*)d_in[11];
    (void)in_sizes; (void)n_in; (void)out_size;

    float* out    = (float*)d_out;
    float* allh   = out;
    float* selctx = out + (long)MROWS * H_;
    float* lp     = selctx + B_ * H_;

    constexpr int SMEM3 = 4 * 4 * TILEB;   // <3,4>: 163840, 1 CTA/SM
    constexpr int SMEM1 = 5 * 2 * TILEB;   // <1,5>: 102400, 2 CTAs/SM

    static int attr_set = 0;
    if (!attr_set) {
        cudaFuncSetAttribute((const void*)hmma_gemm<3,4,false>,
                             cudaFuncAttributeMaxDynamicSharedMemorySize, SMEM3);
        cudaFuncSetAttribute((const void*)hmma_gemm<1,5,true>,
                             cudaFuncAttributeMaxDynamicSharedMemorySize, SMEM1);
        attr_set = 1;
    }

    __nv_bfloat16 *whi, *ahi, *xah, *xal, *wihh, *wihl;
    float *xg, *gpart;
    cudaGetSymbolAddress((void**)&whi, g_whi);
    cudaGetSymbolAddress((void**)&ahi, g_ahi);
    cudaGetSymbolAddress((void**)&xah, g_xah);
    cudaGetSymbolAddress((void**)&xal, g_xal);
    cudaGetSymbolAddress((void**)&wihh, g_wihh);
    cudaGetSymbolAddress((void**)&wihl, g_wihl);
    cudaGetSymbolAddress((void**)&xg, g_xg);
    cudaGetSymbolAddress((void**)&gpart, g_part);

    setup_k<<<1, 32>>>(mask);

    conv_gather<<<1024, 256>>>(ids, emb, dapp, xah, xal);
    conv_k<<<1024, 256>>>(Wih, wihh, wihl, (long)G_ * KX / 4);

    // xg = [emb||app] @ W_ih^T + b_ih  (3-term: feeds recurrence, keep accuracy)
    hmma_gemm<3,4,false><<<dim3(MROWS / 128, G_ / 128), 256, SMEM3>>>(
        xah, xal, wihh, wihl, bih, xg, KX, G_, nullptr);

    conv_hi<<<4096, 256>>>(lmw, whi, (long)V_ * H_ / 4);

    lstm_persist<<<LSTM_BLOCKS, 192>>>(dh, dc, Whh, bhh, allh, selctx, ahi);

    // logits = hiddens(bf16) @ lm_w(bf16)^T + lm_b, fused sum-of-exp partials
    hmma_gemm<1,5,true><<<dim3(MROWS / 128, NT_), 256, SMEM1>>>(
        ahi, ahi, whi, whi, lmb, lp, H_, V_, gpart);

    lse_red<<<MROWS / 256, 256>>>();
    sub_k<<<MROWS, 256>>>(lp);
}

// round 17
// speedup vs baseline: 1.0014x; 1.0014x over previous
#include <cuda_runtime.h>
#include <cuda_bf16.h>
#include <cstdint>

#define V_  50257
#define H_  768
#define B_  16
#define T_  128
#define G_  3072          // 4*H
#define KX  1536          // 2*H
#define MROWS 2048        // B*T
#define NT_  393          // logits n-tiles = ceil(V/128)

#define LSTM_BLOCKS 128
#define LSTM_WARPS  6     // units per block; 128*6 = 768 = H_

// ================= scratch (no cudaMalloc allowed) =================
__device__ float g_xg[(long)MROWS * G_];                 // input-side gate projections
__device__ float g_lse[MROWS];                           // per-row log-sum-exp
__device__ float g_part[(long)MROWS * NT_];              // per (row, n-tile) exp-sum partials
__device__ int   g_last[B_];
__device__ unsigned g_bar;                               // grid barrier counter
__device__ __nv_bfloat16 g_whi[(long)V_ * H_];           // lm_w hi (bf16)
__device__ __nv_bfloat16 g_ahi[(long)MROWS * H_];        // hiddens hi (bf16)
__device__ __nv_bfloat16 g_xah[(long)MROWS * KX];        // [emb||app] hi
__device__ __nv_bfloat16 g_xal[(long)MROWS * KX];        // [emb||app] lo
__device__ __nv_bfloat16 g_wihh[(long)G_ * KX];          // W_ih hi
__device__ __nv_bfloat16 g_wihl[(long)G_ * KX];          // W_ih lo

// ================= small ptx helpers (baseline PTX only) =================
__device__ __forceinline__ uint32_t smem_to_u32(const void* p) {
    uint32_t a;
    asm("{ .reg .u64 t; cvta.to.shared.u64 t, %1; cvt.u32.u64 %0, t; }" : "=r"(a) : "l"(p));
    return a;
}
__device__ __forceinline__ void cpasync16(uint32_t dst, const void* src, uint32_t sz) {
    asm volatile("cp.async.cg.shared.global [%0], [%1], 16, %2;\n"
        :: "r"(dst), "l"(src), "r"(sz) : "memory");
}
__device__ __forceinline__ void ldm_x4(uint32_t addr, uint32_t* r) {
    asm volatile("ldmatrix.sync.aligned.m8n8.x4.shared.b16 {%0,%1,%2,%3}, [%4];"
        : "=r"(r[0]), "=r"(r[1]), "=r"(r[2]), "=r"(r[3]) : "r"(addr));
}
__device__ __forceinline__ void mma16816(float* d, const uint32_t* a, const uint32_t* b) {
    asm volatile("mma.sync.aligned.m16n8k16.row.col.f32.bf16.bf16.f32 "
        "{%0,%1,%2,%3}, {%4,%5,%6,%7}, {%8,%9}, {%0,%1,%2,%3};"
        : "+f"(d[0]), "+f"(d[1]), "+f"(d[2]), "+f"(d[3])
        : "r"(a[0]), "r"(a[1]), "r"(a[2]), "r"(a[3]), "r"(b[0]), "r"(b[1]));
}
__device__ __forceinline__ unsigned ld_acq(const unsigned* p) {
    unsigned v;
    asm volatile("ld.acquire.gpu.global.u32 %0, [%1];" : "=r"(v) : "l"(p) : "memory");
    return v;
}
__device__ __forceinline__ void red_release_add(unsigned* p, unsigned v) {
    asm volatile("red.release.gpu.global.add.u32 [%0], %1;" :: "l"(p), "r"(v) : "memory");
}
// packed f32x2 FMA (sm_100-family): d = a*b + d on two lanes at once
__device__ __forceinline__ void ffma2(uint64_t& d, uint64_t a, uint64_t b) {
    asm("fma.rn.f32x2 %0, %1, %2, %0;" : "+l"(d) : "l"(a), "l"(b));
}
__device__ __forceinline__ uint64_t pk(float lo, float hi) {
    uint64_t r;
    asm("mov.b64 %0, {%1, %2};" : "=l"(r) : "f"(lo), "f"(hi));
    return r;
}
__device__ __forceinline__ uint64_t pk2(float v) { return pk(v, v); }
__device__ __forceinline__ void unpk(uint64_t p, float& lo, float& hi) {
    asm("mov.b64 {%0, %1}, %2;" : "=f"(lo), "=f"(hi) : "l"(p));
}

// ================= fast exp (FMA-only; valid for x in [-20, ~80]) =================
__device__ __forceinline__ float fexp(float x) {
    x = fmaxf(x, -20.0f);
    float t  = x * 1.4426950408889634f;
    float z  = t + 12582912.0f;
    float nf = z - 12582912.0f;
    float f  = t - nf;
    int   n  = (int)nf;
    float p = fmaf(0.00133335581f, f, 0.00961812911f);
    p = fmaf(p, f, 0.0555041087f);
    p = fmaf(p, f, 0.240226507f);
    p = fmaf(p, f, 0.69314718056f);
    p = fmaf(p, f, 1.0f);
    return p * __int_as_float((n + 127) << 23);
}

// ================= setup =================
__global__ void setup_k(const int* __restrict__ mask) {
    int idx = threadIdx.x;
    if (idx < B_) {
        int s = 0;
        for (int t = 0; t < T_; t++) s += mask[idx * T_ + t];
        g_last[idx] = s - 1;
    }
    if (idx == B_) g_bar = 0u;
}

// ================= hi/lo bf16 conversions =================
__global__ void conv_k(const float* __restrict__ src, __nv_bfloat16* __restrict__ hi,
                       __nv_bfloat16* __restrict__ lo, long n4) {
    long i = (long)blockIdx.x * 256 + threadIdx.x;
    long stride = (long)gridDim.x * 256;
    for (; i < n4; i += stride) {
        float4 v = ((const float4*)src)[i];
        __nv_bfloat16 h0 = __float2bfloat16(v.x), h1 = __float2bfloat16(v.y);
        __nv_bfloat16 h2 = __float2bfloat16(v.z), h3 = __float2bfloat16(v.w);
        __nv_bfloat16 l0 = __float2bfloat16(v.x - __bfloat162float(h0));
        __nv_bfloat16 l1 = __float2bfloat16(v.y - __bfloat162float(h1));
        __nv_bfloat16 l2 = __float2bfloat16(v.z - __bfloat162float(h2));
        __nv_bfloat16 l3 = __float2bfloat16(v.w - __bfloat162float(h3));
        ((__nv_bfloat162*)hi)[i * 2 + 0] = __nv_bfloat162(h0, h1);
        ((__nv_bfloat162*)hi)[i * 2 + 1] = __nv_bfloat162(h2, h3);
        ((__nv_bfloat162*)lo)[i * 2 + 0] = __nv_bfloat162(l0, l1);
        ((__nv_bfloat162*)lo)[i * 2 + 1] = __nv_bfloat162(l2, l3);
    }
}

// hi-only conversion (for lm_w: 1-term logits GEMM needs no residual)
__global__ void conv_hi(const float* __restrict__ src, __nv_bfloat16* __restrict__ hi, long n4) {
    long i = (long)blockIdx.x * 256 + threadIdx.x;
    long stride = (long)gridDim.x * 256;
    for (; i < n4; i += stride) {
        float4 v = ((const float4*)src)[i];
        ((__nv_bfloat162*)hi)[i * 2 + 0] =
            __nv_bfloat162(__float2bfloat16(v.x), __float2bfloat16(v.y));
        ((__nv_bfloat162*)hi)[i * 2 + 1] =
            __nv_bfloat162(__float2bfloat16(v.z), __float2bfloat16(v.w));
    }
}

// build [emb(ids) || append] as hi/lo bf16, rows = MROWS, K = KX
__global__ void conv_gather(const int* __restrict__ ids, const float* __restrict__ emb,
                            const float* __restrict__ app,
                            __nv_bfloat16* __restrict__ hi, __nv_bfloat16* __restrict__ lo) {
    long total = (long)MROWS * (KX / 4);
    long i = (long)blockIdx.x * 256 + threadIdx.x;
    long stride = (long)gridDim.x * 256;
    for (; i < total; i += stride) {
        int m = (int)(i / (KX / 4));
        int q = (int)(i - (long)m * (KX / 4));
        int k = q * 4;
        const float* p;
        if (k < H_) p = emb + (long)ids[m] * H_ + k;
        else        p = app + (long)(m >> 7) * H_ + (k - H_);
        float4 v = *(const float4*)p;
        __nv_bfloat16 h0 = __float2bfloat16(v.x), h1 = __float2bfloat16(v.y);
        __nv_bfloat16 h2 = __float2bfloat16(v.z), h3 = __float2bfloat16(v.w);
        __nv_bfloat16 l0 = __float2bfloat16(v.x - __bfloat162float(h0));
        __nv_bfloat16 l1 = __float2bfloat16(v.y - __bfloat162float(h1));
        __nv_bfloat16 l2 = __float2bfloat16(v.z - __bfloat162float(h2));
        __nv_bfloat16 l3 = __float2bfloat16(v.w - __bfloat162float(h3));
        long o = (long)m * (KX / 2) + q * 2;
        ((__nv_bfloat162*)hi)[o + 0] = __nv_bfloat162(h0, h1);
        ((__nv_bfloat162*)hi)[o + 1] = __nv_bfloat162(h2, h3);
        ((__nv_bfloat162*)lo)[o + 0] = __nv_bfloat162(l0, l1);
        ((__nv_bfloat162*)lo)[o + 1] = __nv_bfloat162(l2, l3);
    }
}

// ================= HMMA GEMM (templated terms/stages/fused-sum): C = A @ B^T + bias ====
// Block 128x128, warp tile 64x32 (8 warps 2m x 4n), BK=32, NST-stage cp.async pipeline,
// ONE __syncthreads per K-chunk.
// NTERMS=3: AhBh+AhBl+AlBh (1 CTA/SM). NTERMS=1: AhBh only (2 CTAs/SM).
// FUSE: additionally emits deterministic per-(row, n-tile) sum-of-exp partials to part[].
#define LDSW  80                     // padded row stride bytes (64B data + 16B pad)
#define TILEB (128 * LDSW)           // 10240 B per 128-row tile

template<int NTERMS, int NST, bool FUSE>
__global__ __launch_bounds__(256, (NTERMS == 1 ? 2 : 1)) void hmma_gemm(
    const __nv_bfloat16* __restrict__ Ah, const __nv_bfloat16* __restrict__ Al,
    const __nv_bfloat16* __restrict__ Bh, const __nv_bfloat16* __restrict__ Bl,
    const float* __restrict__ bias, float* __restrict__ C,
    int K, int Nvalid, float* __restrict__ part)
{
    constexpr int NMAT  = (NTERMS == 3) ? 4 : (NTERMS == 2 ? 3 : 2);
    constexpr int STAGE = NMAT * TILEB;
    // stage layout: Ah @0, Bh @TILEB, [Bl @2*TILEB], [Al @3*TILEB]

    extern __shared__ __align__(128) char smem[];
    uint32_t sb = smem_to_u32(smem);
    int tid = threadIdx.x;
    int lane = tid & 31, wid = tid >> 5;
    int wm = wid & 1, wn = wid >> 1;
    int m0 = blockIdx.x * 128;          // m-fast for B-tile L2 reuse
    int n0 = blockIdx.y * 128;
    int NK = K >> 5;

    float acc[4][4][4];
#pragma unroll
    for (int a = 0; a < 4; a++)
#pragma unroll
        for (int b = 0; b < 4; b++)
#pragma unroll
            for (int c = 0; c < 4; c++) acc[a][b][c] = 0.0f;

    int lrow = tid >> 2;     // 0..63
    int lq   = tid & 3;

    auto load_stage = [&](int stg) {
        int k0 = stg << 5;
        uint32_t db = sb + (stg % NST) * STAGE;
#pragma unroll
        for (int half = 0; half < 2; half++) {
            int r = half * 64 + lrow;
            uint32_t dof = (uint32_t)(r * LDSW + lq * 16);
            long asrc = (long)(m0 + r) * K + k0 + lq * 8;
            cpasync16(db + dof, Ah + asrc, 16);
            if (NTERMS == 3) cpasync16(db + 3 * TILEB + dof, Al + asrc, 16);
            int n = n0 + r;
            uint32_t sz = 16;
            if (n >= Nvalid) { n = 0; sz = 0; }
            long bsrc = (long)n * K + k0 + lq * 8;
            cpasync16(db + TILEB + dof, Bh + bsrc, sz);
            if (NTERMS >= 2) cpasync16(db + 2 * TILEB + dof, Bl + bsrc, sz);
        }
    };

    // prologue: fill NST-1 stages
#pragma unroll
    for (int s = 0; s < NST - 1; s++) {
        if (s < NK) load_stage(s);
        asm volatile("cp.async.commit_group;" ::: "memory");
    }

    int a_row = lane & 15;
    int a_kh  = (lane >> 4) << 3;
    int b_g   = lane >> 3;
    int b_nr  = ((b_g >> 1) << 3) + (lane & 7);
    int b_kh  = (b_g & 1) << 3;

    for (int c = 0; c < NK; c++) {
        asm volatile("cp.async.wait_group %0;" :: "n"(NST - 2) : "memory");
        __syncthreads();

        // refill stage c+NST-1 (that buffer was last read in chunk c-1; safe after sync)
        if (c + NST - 1 < NK) load_stage(c + NST - 1);
        asm volatile("cp.async.commit_group;" ::: "memory");

        uint32_t aB = sb + (c % NST) * STAGE;
#pragma unroll
        for (int kk = 0; kk < 32; kk += 16) {
            uint32_t bh[8], bl[8], ah[16], al[16];
#pragma unroll
            for (int f2 = 0; f2 < 2; f2++) {
                uint32_t off = (uint32_t)((wn * 32 + f2 * 16 + b_nr) * LDSW + (kk + b_kh) * 2);
                ldm_x4(aB + TILEB + off, &bh[f2 * 4]);
                if (NTERMS >= 2) ldm_x4(aB + 2 * TILEB + off, &bl[f2 * 4]);
            }
#pragma unroll
            for (int fm = 0; fm < 4; fm++) {
                uint32_t off = (uint32_t)((wm * 64 + fm * 16 + a_row) * LDSW + (kk + a_kh) * 2);
                ldm_x4(aB + off, &ah[fm * 4]);
                if (NTERMS == 3) ldm_x4(aB + 3 * TILEB + off, &al[fm * 4]);
            }
#pragma unroll
            for (int fm = 0; fm < 4; fm++)
#pragma unroll
                for (int fn = 0; fn < 4; fn++) {
                    mma16816(acc[fm][fn], &ah[fm * 4], &bh[fn * 2]);
                    if (NTERMS >= 2) mma16816(acc[fm][fn], &ah[fm * 4], &bl[fn * 2]);
                    if (NTERMS == 3) mma16816(acc[fm][fn], &al[fm * 4], &bh[fn * 2]);
                }
        }
    }

    // epilogue: direct stores + bias; FUSE also accumulates sum-of-exp per row
    int mbase = m0 + wm * 64 + (lane >> 2);
    int nbase = n0 + wn * 32 + ((lane & 3) << 1);
    float es_lo[4], es_hi[4];
    if (FUSE) {
#pragma unroll
        for (int i = 0; i < 4; i++) { es_lo[i] = 0.0f; es_hi[i] = 0.0f; }
    }
#pragma unroll
    for (int fm = 0; fm < 4; fm++) {
#pragma unroll
        for (int fn = 0; fn < 4; fn++) {
            int m = mbase + fm * 16;
            int n = nbase + fn * 8;
            float* d = acc[fm][fn];
            if (n < Nvalid) {
                float bv = bias[n];
                float v0 = d[0] + bv, v2 = d[2] + bv;
                C[(long)m * Nvalid + n]       = v0;
                C[(long)(m + 8) * Nvalid + n] = v2;
                if (FUSE) { es_lo[fm] += fexp(v0); es_hi[fm] += fexp(v2); }
            }
            if (n + 1 < Nvalid) {
                float bv = bias[n + 1];
                float v1 = d[1] + bv, v3 = d[3] + bv;
                C[(long)m * Nvalid + n + 1]       = v1;
                C[(long)(m + 8) * Nvalid + n + 1] = v3;
                if (FUSE) { es_lo[fm] += fexp(v1); es_hi[fm] += fexp(v3); }
            }
        }
    }
    if (FUSE) {
        // deterministic: quad-shfl -> one writer per (row, wn) -> fixed-order sum
        __syncthreads();                 // smem stages no longer needed
        float* rsum = (float*)smem;      // [128][4]
#pragma unroll
        for (int fm = 0; fm < 4; fm++) {
            float el = es_lo[fm], eh = es_hi[fm];
            el += __shfl_xor_sync(0xffffffffu, el, 1);
            el += __shfl_xor_sync(0xffffffffu, el, 2);
            eh += __shfl_xor_sync(0xffffffffu, eh, 1);
            eh += __shfl_xor_sync(0xffffffffu, eh, 2);
            if ((lane & 3) == 0) {
                int rl = wm * 64 + fm * 16 + (lane >> 2);
                rsum[rl * 4 + wn] = el;
                rsum[(rl + 8) * 4 + wn] = eh;
            }
        }
        __syncthreads();
        if (tid < 128) {
            float s = rsum[tid * 4 + 0] + rsum[tid * 4 + 1]
                    + rsum[tid * 4 + 2] + rsum[tid * 4 + 3];
            part[(long)(m0 + tid) * NT_ + blockIdx.y] = s;
        }
    }
}

// ================= lse reduce: fixed-order sum of partials, then log =================
__global__ void lse_red() {
    int m = blockIdx.x * 256 + threadIdx.x;
    if (m < MROWS) {
        const float* p = g_part + (long)m * NT_;
        float s = 0.0f;
        for (int i = 0; i < NT_; i++) s += p[i];
        g_lse[m] = logf(s);
    }
}

// ================= final subtract =================
__global__ void sub_k(float* __restrict__ lp) {
    int m = blockIdx.x;
    float l = g_lse[m];
    float* row = lp + (long)m * V_;
    for (int j = threadIdx.x; j < V_; j += 256) row[j] -= l;
}

// ================= persistent LSTM recurrence (f32x2-packed gates GEMM) ==============
__global__ __launch_bounds__(192) void lstm_persist(
    const float* __restrict__ dh, const float* __restrict__ dctx,
    const float* __restrict__ Whh, const float* __restrict__ bhh,
    float* __restrict__ allh, float* __restrict__ selctx,
    __nv_bfloat16* __restrict__ ahi)
{
    __shared__ __align__(16) float hs[B_ * H_];
    int tid = threadIdx.x, wid = tid >> 5, lane = tid & 31;
    int u = blockIdx.x * LSTM_WARPS + wid;

    const float4* wp0 = (const float4*)(Whh + (long)(0 * H_ + u) * H_);
    const float4* wp1 = (const float4*)(Whh + (long)(1 * H_ + u) * H_);
    const float4* wp2 = (const float4*)(Whh + (long)(2 * H_ + u) * H_);
    const float4* wp3 = (const float4*)(Whh + (long)(3 * H_ + u) * H_);
    const float4* h4 = (const float4*)hs;

    float creg = 0.0f, b0r = 0.0f, b1r = 0.0f, b2r = 0.0f, b3r = 0.0f;
    float x0 = 0.f, x1 = 0.f, x2 = 0.f, x3 = 0.f;
    int lastb = 0;
    if (lane < 16) {
        creg = dctx[lane * H_ + u];
        lastb = g_last[lane];
        b0r = bhh[0 * H_ + u]; b1r = bhh[1 * H_ + u];
        b2r = bhh[2 * H_ + u]; b3r = bhh[3 * H_ + u];
        const float* xr = g_xg + ((long)lane * T_ + 0) * G_;
        x0 = xr[0 * H_ + u]; x1 = xr[1 * H_ + u];
        x2 = xr[2 * H_ + u]; x3 = xr[3 * H_ + u];
    }

    for (int t = 0; t < T_; t++) {
        float nx0 = 0.f, nx1 = 0.f, nx2 = 0.f, nx3 = 0.f;
        if (lane < 16 && t + 1 < T_) {
            const float* xr = g_xg + ((long)lane * T_ + t + 1) * G_;
            nx0 = __ldcg(xr + 0 * H_ + u); nx1 = __ldcg(xr + 1 * H_ + u);
            nx2 = __ldcg(xr + 2 * H_ + u); nx3 = __ldcg(xr + 3 * H_ + u);
        }

        if (t == 0) {
            for (int i4 = tid; i4 < B_ * H_ / 4; i4 += 192)
                ((float4*)hs)[i4] = __ldcg((const float4*)dh + i4);
        } else {
            for (int i4 = tid; i4 < B_ * H_ / 4; i4 += 192) {
                int b = i4 / (H_ / 4), q = i4 - b * (H_ / 4);
                ((float4*)hs)[i4] = __ldcg((const float4*)(allh + ((long)b * T_ + t - 1) * H_) + q);
            }
        }
        __syncthreads();

        // gates GEMM: pack batch pairs into f32x2 -> half the fma-pipe cycles
        uint64_t acc2[4][8];
#pragma unroll
        for (int g = 0; g < 4; g++)
#pragma unroll
            for (int bp = 0; bp < 8; bp++) acc2[g][bp] = 0ull;

#pragma unroll
        for (int ch = 0; ch < 6; ch++) {
            int k4 = ch * 32 + lane;
            float4 w0 = wp0[k4], w1 = wp1[k4], w2 = wp2[k4], w3 = wp3[k4];
            uint64_t w0x = pk2(w0.x), w0y = pk2(w0.y), w0z = pk2(w0.z), w0w = pk2(w0.w);
            uint64_t w1x = pk2(w1.x), w1y = pk2(w1.y), w1z = pk2(w1.z), w1w = pk2(w1.w);
            uint64_t w2x = pk2(w2.x), w2y = pk2(w2.y), w2z = pk2(w2.z), w2w = pk2(w2.w);
            uint64_t w3x = pk2(w3.x), w3y = pk2(w3.y), w3z = pk2(w3.z), w3w = pk2(w3.w);
#pragma unroll
            for (int bp = 0; bp < 8; bp++) {
                float4 hA = h4[(2 * bp) * 192 + k4];
                float4 hB = h4[(2 * bp + 1) * 192 + k4];
                uint64_t hx = pk(hA.x, hB.x), hy = pk(hA.y, hB.y);
                uint64_t hz = pk(hA.z, hB.z), hw = pk(hA.w, hB.w);
                ffma2(acc2[0][bp], w0x, hx); ffma2(acc2[0][bp], w0y, hy);
                ffma2(acc2[0][bp], w0z, hz); ffma2(acc2[0][bp], w0w, hw);
                ffma2(acc2[1][bp], w1x, hx); ffma2(acc2[1][bp], w1y, hy);
                ffma2(acc2[1][bp], w1z, hz); ffma2(acc2[1][bp], w1w, hw);
                ffma2(acc2[2][bp], w2x, hx); ffma2(acc2[2][bp], w2y, hy);
                ffma2(acc2[2][bp], w2z, hz); ffma2(acc2[2][bp], w2w, hw);
                ffma2(acc2[3][bp], w3x, hx); ffma2(acc2[3][bp], w3y, hy);
                ffma2(acc2[3][bp], w3z, hz); ffma2(acc2[3][bp], w3w, hw);
            }
        }

        float acc[4][16];
#pragma unroll
        for (int g = 0; g < 4; g++)
#pragma unroll
            for (int bp = 0; bp < 8; bp++)
                unpk(acc2[g][bp], acc[g][2 * bp], acc[g][2 * bp + 1]);

#pragma unroll
        for (int g = 0; g < 4; g++)
#pragma unroll
            for (int b = 0; b < 16; b++) {
                float v = acc[g][b];
#pragma unroll
                for (int off = 16; off; off >>= 1) v += __shfl_xor_sync(0xffffffffu, v, off);
                acc[g][b] = v;
            }

        if (lane < 16) {
            int b = lane;
            long m = (long)b * T_ + t;
            float xi = acc[0][b] + x0 + b0r;
            float xf = acc[1][b] + x1 + b1r;
            float xg = acc[2][b] + x2 + b2r;
            float xo = acc[3][b] + x3 + b3r;
            float si = 1.0f / (1.0f + expf(-xi));
            float sf = 1.0f / (1.0f + expf(-xf));
            float so = 1.0f / (1.0f + expf(-xo));
            float tg = tanhf(xg);
            creg = sf * creg + si * tg;
            float h = so * tanhf(creg);
            allh[m * H_ + u] = h;
            ahi[m * H_ + u] = __float2bfloat16(h);
            if (t == lastb) selctx[b * H_ + u] = creg;
        }
        x0 = nx0; x1 = nx1; x2 = nx2; x3 = nx3;

        if (t + 1 < T_) {
            __syncthreads();              // orders all threads' h-stores before tid0's release
            if (tid == 0) {
                red_release_add(&g_bar, 1u);   // cumulative release publishes block's writes
                unsigned tgt = (unsigned)(LSTM_BLOCKS * (t + 1));
                while (ld_acq(&g_bar) < tgt) { }
            }
            __syncthreads();
        }
    }
}

// ================= launch =================
extern "C" void kernel_launch(void* const* d_in, const int* in_sizes, int n_in,
                              void* d_out, int out_size)
{
    const int*   ids  = (const int*)d_in[0];
    const int*   mask = (const int*)d_in[1];
    const float* dh   = (const float*)d_in[2];
    const float* dc   = (const float*)d_in[3];
    const float* dapp = (const float*)d_in[4];
    const float* emb  = (const float*)d_in[5];
    const float* Wih  = (const float*)d_in[6];
    const float* Whh  = (const float*)d_in[7];
    const float* bih  = (const float*)d_in[8];
    const float* bhh  = (const float*)d_in[9];
    const float* lmw  = (const float*)d_in[10];
    const float* lmb  = (const float*)d_in[11];
    (void)in_sizes; (void)n_in; (void)out_size;

    float* out    = (float*)d_out;
    float* allh   = out;
    float* selctx = out + (long)MROWS * H_;
    float* lp     = selctx + B_ * H_;

    constexpr int SMEM3 = 4 * 4 * TILEB;   // <3,4>: 163840, 1 CTA/SM
    constexpr int SMEM1 = 5 * 2 * TILEB;   // <1,5>: 102400, 2 CTAs/SM

    static int attr_set = 0;
    if (!attr_set) {
        cudaFuncSetAttribute((const void*)hmma_gemm<3,4,false>,
                             cudaFuncAttributeMaxDynamicSharedMemorySize, SMEM3);
        cudaFuncSetAttribute((const void*)hmma_gemm<1,5,true>,
                             cudaFuncAttributeMaxDynamicSharedMemorySize, SMEM1);
        attr_set = 1;
    }

    __nv_bfloat16 *whi, *ahi, *xah, *xal, *wihh, *wihl;
    float *xg, *gpart;
    cudaGetSymbolAddress((void**)&whi, g_whi);
    cudaGetSymbolAddress((void**)&ahi, g_ahi);
    cudaGetSymbolAddress((void**)&xah, g_xah);
    cudaGetSymbolAddress((void**)&xal, g_xal);
    cudaGetSymbolAddress((void**)&wihh, g_wihh);
    cudaGetSymbolAddress((void**)&wihl, g_wihl);
    cudaGetSymbolAddress((void**)&xg, g_xg);
    cudaGetSymbolAddress((void**)&gpart, g_part);

    setup_k<<<1, 32>>>(mask);

    conv_gather<<<1024, 256>>>(ids, emb, dapp, xah, xal);
    conv_k<<<1024, 256>>>(Wih, wihh, wihl, (long)G_ * KX / 4);

    // xg = [emb||app] @ W_ih^T + b_ih  (3-term: feeds recurrence, keep accuracy)
    hmma_gemm<3,4,false><<<dim3(MROWS / 128, G_ / 128), 256, SMEM3>>>(
        xah, xal, wihh, wihl, bih, xg, KX, G_, nullptr);

    conv_hi<<<4096, 256>>>(lmw, whi, (long)V_ * H_ / 4);

    lstm_persist<<<LSTM_BLOCKS, 192>>>(dh, dc, Whh, bhh, allh, selctx, ahi);

    // logits = hiddens(bf16) @ lm_w(bf16)^T + lm_b, fused sum-of-exp partials
    hmma_gemm<1,5,true><<<dim3(MROWS / 128, NT_), 256, SMEM1>>>(
        ahi, ahi, whi, whi, lmb, lp, H_, V_, gpart);

    lse_red<<<MROWS / 256, 256>>>();
    sub_k<<<MROWS, 256>>>(lp);
}